// round 2
// baseline (speedup 1.0000x reference)
#include <cuda_runtime.h>
#include <math.h>

#define N 4096
#define D 512
#define NN (N * N)

// log2-domain scale: (1/EPS) * log2(e)
#define KSCALE 14.4269504088896340736f
// EPS * ln2 / N
#define OUT_SCALE (0.1 * 0.69314718055994530942 / 4096.0)

// ---------------- device scratch (no allocations allowed) ----------------
__device__ float d_Cxy[NN];
__device__ float d_Cyx[NN];
__device__ float d_Cxx[NN];
__device__ float d_Cyy[NN];
__device__ float d_xsq[N];
__device__ float d_ysq[N];
__device__ float d_F[3][N];
__device__ float d_G[3][N];
__device__ float d_L[2][3][N];   // [phase][problem][row]: previous log2-sum per row

__device__ __forceinline__ float ex2f(float x) {
    float y;
    asm("ex2.approx.ftz.f32 %0, %1;" : "=f"(y) : "f"(x));
    return y;
}

// ---------------- row sum-of-squares ----------------
__global__ void rowsq_kernel(const float* __restrict__ X, float* __restrict__ out) {
    int row = blockIdx.x * 8 + threadIdx.y;
    const float* xr = X + (size_t)row * D;
    float s = 0.f;
    for (int k = threadIdx.x; k < D; k += 32) {
        float v = __ldg(xr + k);
        s = fmaf(v, v, s);
    }
    #pragma unroll
    for (int off = 16; off > 0; off >>= 1)
        s += __shfl_down_sync(0xffffffffu, s, off);
    if (threadIdx.x == 0) out[row] = s;
}

// ---------------- cost GEMM (double-buffered smem) ----------------
// Cout[i][j] = clip(a2[i]+b2[j]-2*dot,0,1e6)*KSCALE
// SYM variant: A==B, computes upper-triangle tiles only and mirror-writes.
#define GBM 128
#define GBN 128
#define GBK 8

template <bool SYM>
__global__ __launch_bounds__(256) void gemm_cost_kernel(
    const float* __restrict__ A, const float* __restrict__ B,
    const float* __restrict__ a2, const float* __restrict__ b2,
    float* __restrict__ Cout)
{
    if (SYM && blockIdx.x < blockIdx.y) return;  // keep gj-tile >= gi-tile

    __shared__ float As[2][GBK][GBM];
    __shared__ float Bs[2][GBK][GBN];
    const int tid  = threadIdx.x;
    const int irow = tid >> 1;
    const int icol = (tid & 1) * 4;
    const int trow = (tid >> 4) * 8;
    const int tcol = (tid & 15) * 8;

    const float* Aptr = A + (size_t)(blockIdx.y * GBM + irow) * D + icol;
    const float* Bptr = B + (size_t)(blockIdx.x * GBN + irow) * D + icol;

    float acc[8][8];
    #pragma unroll
    for (int i = 0; i < 8; i++)
        #pragma unroll
        for (int j = 0; j < 8; j++) acc[i][j] = 0.f;

    // prologue: fill buffer 0
    {
        float4 av = *(const float4*)(Aptr);
        float4 bv = *(const float4*)(Bptr);
        As[0][icol + 0][irow] = av.x; As[0][icol + 1][irow] = av.y;
        As[0][icol + 2][irow] = av.z; As[0][icol + 3][irow] = av.w;
        Bs[0][icol + 0][irow] = bv.x; Bs[0][icol + 1][irow] = bv.y;
        Bs[0][icol + 2][irow] = bv.z; Bs[0][icol + 3][irow] = bv.w;
    }
    __syncthreads();

    int p = 0;
    for (int k0 = GBK; k0 <= D; k0 += GBK) {
        const bool last = (k0 == D);
        float4 av, bv;
        if (!last) {
            av = *(const float4*)(Aptr + k0);
            bv = *(const float4*)(Bptr + k0);
        }
        #pragma unroll
        for (int k = 0; k < GBK; k++) {
            float ar[8], br[8];
            #pragma unroll
            for (int i = 0; i < 8; i++) ar[i] = As[p][k][trow + i];
            #pragma unroll
            for (int j = 0; j < 8; j++) br[j] = Bs[p][k][tcol + j];
            #pragma unroll
            for (int i = 0; i < 8; i++)
                #pragma unroll
                for (int j = 0; j < 8; j++)
                    acc[i][j] = fmaf(ar[i], br[j], acc[i][j]);
        }
        if (!last) {
            const int q = p ^ 1;
            As[q][icol + 0][irow] = av.x; As[q][icol + 1][irow] = av.y;
            As[q][icol + 2][irow] = av.z; As[q][icol + 3][irow] = av.w;
            Bs[q][icol + 0][irow] = bv.x; Bs[q][icol + 1][irow] = bv.y;
            Bs[q][icol + 2][irow] = bv.z; Bs[q][icol + 3][irow] = bv.w;
            __syncthreads();
            p = q;
        }
    }

    const int gi = blockIdx.y * GBM + trow;
    const int gj = blockIdx.x * GBN + tcol;

    // finalize values in-place
    #pragma unroll
    for (int i = 0; i < 8; i++) {
        float ai = __ldg(a2 + gi + i);
        #pragma unroll
        for (int j = 0; j < 8; j++) {
            float c = ai + __ldg(b2 + gj + j) - 2.0f * acc[i][j];
            c = fminf(fmaxf(c, 0.0f), 1.0e6f);
            acc[i][j] = c * KSCALE;
        }
    }

    // normal write: row gi+i, cols gj+j
    #pragma unroll
    for (int i = 0; i < 8; i++) {
        float* crow = Cout + (size_t)(gi + i) * N + gj;
        #pragma unroll
        for (int j = 0; j < 8; j++) crow[j] = acc[i][j];
    }

    // mirror write for symmetric off-diagonal tiles: (gj+j, gi+i) = same value
    if (SYM && blockIdx.x != blockIdx.y) {
        #pragma unroll
        for (int j = 0; j < 8; j++) {
            float* crow = Cout + (size_t)(gj + j) * N + gi;
            #pragma unroll
            for (int i = 0; i < 8; i++) crow[i] = acc[i][j];
        }
    }
}

// ---------------- transpose (Cyx = Cxy^T) ----------------
__global__ void transpose_kernel(const float* __restrict__ in, float* __restrict__ out) {
    __shared__ float tile[32][33];
    int x = blockIdx.x * 32 + threadIdx.x;
    int y = blockIdx.y * 32 + threadIdx.y;
    #pragma unroll
    for (int r = 0; r < 32; r += 8)
        tile[threadIdx.y + r][threadIdx.x] = in[(size_t)(y + r) * N + x];
    __syncthreads();
    int xo = blockIdx.y * 32 + threadIdx.x;
    int yo = blockIdx.x * 32 + threadIdx.y;
    #pragma unroll
    for (int r = 0; r < 32; r += 8)
        out[(size_t)(yo + r) * N + xo] = tile[threadIdx.x][threadIdx.y + r];
}

// ---------------- potential init ----------------
__global__ void init_pot_kernel() {
    int i = blockIdx.x * 256 + threadIdx.x;
    if (i < 3 * N) {
        (&d_F[0][0])[i] = 0.f;
        (&d_G[0][0])[i] = 0.f;
    }
}

// ---------------- matrix select helper ----------------
__device__ __forceinline__ const float* pick_matrix(int p, int phase) {
    if (p == 0) return (phase == 0) ? d_Cxy : d_Cyx;
    if (p == 1) return d_Cxx;
    return d_Cyy;
}

// ---------------- robust half-iteration (online max LSE), writes L ----------
__device__ __forceinline__ void lse_up(float& m, float& s, float a) {
    if (a <= m) {
        s += ex2f(a - m);
    } else {
        s = fmaf(s, ex2f(m - a), 1.0f);
        m = a;
    }
}

__global__ __launch_bounds__(256) void lse_robust_kernel(int phase) {
    const int p = blockIdx.y;
    const float* M = pick_matrix(p, phase);
    const float* vin = (phase == 0) ? d_G[p] : d_F[p];
    float* vout      = (phase == 0) ? d_F[p] : d_G[p];

    const int row = blockIdx.x;
    const float* Mr = M + (size_t)row * N;
    const int t4 = threadIdx.x * 4;

    float m = __int_as_float(0xff800000);  // -inf
    float s = 0.f;
    #pragma unroll
    for (int k = 0; k < 4; k++) {
        int j = t4 + k * 1024;
        float4 mv = *(const float4*)(Mr + j);
        float4 vv = *(const float4*)(vin + j);
        lse_up(m, s, vv.x - mv.x);
        lse_up(m, s, vv.y - mv.y);
        lse_up(m, s, vv.z - mv.z);
        lse_up(m, s, vv.w - mv.w);
    }

    __shared__ float sm[256], ss[256];
    sm[threadIdx.x] = m;
    ss[threadIdx.x] = s;
    __syncthreads();
    for (int off = 128; off > 0; off >>= 1) {
        if (threadIdx.x < off) {
            float m1 = sm[threadIdx.x], s1 = ss[threadIdx.x];
            float m2 = sm[threadIdx.x + off], s2 = ss[threadIdx.x + off];
            float mm = fmaxf(m1, m2);
            sm[threadIdx.x] = mm;
            ss[threadIdx.x] = fmaf(s1, ex2f(m1 - mm), s2 * ex2f(m2 - mm));
        }
        __syncthreads();
    }
    if (threadIdx.x == 0) {
        float L = sm[0] + log2f(ss[0]);
        vout[row] = 12.0f - L;
        d_L[phase][p][row] = L;
    }
}

// ---------------- fast half-iteration: shift by previous L (branch-free) ----
__global__ __launch_bounds__(256) void lse_fast_kernel(int phase) {
    const int p = blockIdx.y;
    const float* M = pick_matrix(p, phase);
    const float* vin = (phase == 0) ? d_G[p] : d_F[p];
    float* vout      = (phase == 0) ? d_F[p] : d_G[p];

    const int row = blockIdx.x;
    const float Lp = d_L[phase][p][row];
    const float* Mr = M + (size_t)row * N;
    const int t4 = threadIdx.x * 4;

    float s0 = 0.f, s1 = 0.f, s2 = 0.f, s3 = 0.f;
    #pragma unroll
    for (int k = 0; k < 4; k++) {
        int j = t4 + k * 1024;
        float4 mv = *(const float4*)(Mr + j);
        float4 vv = *(const float4*)(vin + j);
        s0 += ex2f((vv.x - Lp) - mv.x);
        s1 += ex2f((vv.y - Lp) - mv.y);
        s2 += ex2f((vv.z - Lp) - mv.z);
        s3 += ex2f((vv.w - Lp) - mv.w);
    }
    float s = (s0 + s1) + (s2 + s3);

    // warp reduce
    #pragma unroll
    for (int off = 16; off > 0; off >>= 1)
        s += __shfl_down_sync(0xffffffffu, s, off);

    __shared__ float sw[8];
    if ((threadIdx.x & 31) == 0) sw[threadIdx.x >> 5] = s;
    __syncthreads();
    if (threadIdx.x == 0) {
        float S = sw[0] + sw[1] + sw[2] + sw[3] + sw[4] + sw[5] + sw[6] + sw[7];
        float Lnew = Lp + log2f(S);
        vout[row] = 12.0f - Lnew;
        d_L[phase][p][row] = Lnew;
    }
}

// ---------------- final scalar reduce ----------------
__global__ __launch_bounds__(256) void final_reduce_kernel(float* __restrict__ out) {
    __shared__ double sh[3][256];
    const int tid = threadIdx.x;
    double acc0 = 0.0, acc1 = 0.0, acc2 = 0.0;
    for (int j = tid; j < N; j += 256) {
        acc0 += (double)d_F[0][j] + (double)d_G[0][j];
        acc1 += (double)d_F[1][j] + (double)d_G[1][j];
        acc2 += (double)d_F[2][j] + (double)d_G[2][j];
    }
    sh[0][tid] = acc0; sh[1][tid] = acc1; sh[2][tid] = acc2;
    __syncthreads();
    for (int off = 128; off > 0; off >>= 1) {
        if (tid < off) {
            sh[0][tid] += sh[0][tid + off];
            sh[1][tid] += sh[1][tid + off];
            sh[2][tid] += sh[2][tid + off];
        }
        __syncthreads();
    }
    if (tid == 0) {
        double Sdiff = sh[0][0] - 0.5 * (sh[1][0] + sh[2][0]);
        double val = Sdiff * OUT_SCALE;
        out[0] = (float)(val > 0.0 ? val : 0.0);
    }
}

// ---------------- launch ----------------
extern "C" void kernel_launch(void* const* d_in, const int* in_sizes, int n_in,
                              void* d_out, int out_size)
{
    const float* x = (const float*)d_in[0];
    const float* y = (const float*)d_in[1];
    float* out = (float*)d_out;

    float *Cxy, *Cyx, *Cxx, *Cyy, *xsq, *ysq;
    cudaGetSymbolAddress((void**)&Cxy, d_Cxy);
    cudaGetSymbolAddress((void**)&Cyx, d_Cyx);
    cudaGetSymbolAddress((void**)&Cxx, d_Cxx);
    cudaGetSymbolAddress((void**)&Cyy, d_Cyy);
    cudaGetSymbolAddress((void**)&xsq, d_xsq);
    cudaGetSymbolAddress((void**)&ysq, d_ysq);

    dim3 rsBlock(32, 8);
    rowsq_kernel<<<N / 8, rsBlock>>>(x, xsq);
    rowsq_kernel<<<N / 8, rsBlock>>>(y, ysq);

    dim3 gGrid(N / GBN, N / GBM);
    gemm_cost_kernel<false><<<gGrid, 256>>>(x, y, xsq, ysq, Cxy);
    gemm_cost_kernel<true ><<<gGrid, 256>>>(x, x, xsq, xsq, Cxx);
    gemm_cost_kernel<true ><<<gGrid, 256>>>(y, y, ysq, ysq, Cyy);

    dim3 tBlock(32, 8);
    dim3 tGrid(N / 32, N / 32);
    transpose_kernel<<<tGrid, tBlock>>>(Cxy, Cyx);

    init_pot_kernel<<<(3 * N + 255) / 256, 256>>>();

    dim3 lGrid(N, 3);
    const int WARMUP = 3;
    for (int it = 0; it < WARMUP; it++) {
        lse_robust_kernel<<<lGrid, 256>>>(0);
        lse_robust_kernel<<<lGrid, 256>>>(1);
    }
    for (int it = WARMUP; it < 50; it++) {
        lse_fast_kernel<<<lGrid, 256>>>(0);
        lse_fast_kernel<<<lGrid, 256>>>(1);
    }

    final_reduce_kernel<<<1, 256>>>(out);
}

// round 3
// speedup vs baseline: 1.3000x; 1.3000x over previous
#include <cuda_runtime.h>
#include <math.h>

#define N 4096
#define D 512
#define NN (N * N)

// log2-domain scale: (1/EPS) * log2(e)
#define KSCALE 14.4269504088896340736f
// EPS * ln2 / N
#define OUT_SCALE (0.1 * 0.69314718055994530942 / 4096.0)

// ---------------- device scratch (no allocations allowed) ----------------
__device__ float d_Cxy[NN];
__device__ float d_Cyx[NN];
__device__ float d_Cxx[NN];
__device__ float d_Cyy[NN];
__device__ float d_xsq[N];
__device__ float d_ysq[N];
__device__ float d_F[3][N];
__device__ float d_G[3][N];
__device__ float d_L[2][3][N];   // [phase][problem][row]: previous log2-sum

__device__ __forceinline__ float ex2f(float x) {
    float y;
    asm("ex2.approx.ftz.f32 %0, %1;" : "=f"(y) : "f"(x));
    return y;
}

// ---------------- row sum-of-squares ----------------
__global__ void rowsq_kernel(const float* __restrict__ X, float* __restrict__ out) {
    int row = blockIdx.x * 8 + threadIdx.y;
    const float* xr = X + (size_t)row * D;
    float s = 0.f;
    for (int k = threadIdx.x; k < D; k += 32) {
        float v = __ldg(xr + k);
        s = fmaf(v, v, s);
    }
    #pragma unroll
    for (int off = 16; off > 0; off >>= 1)
        s += __shfl_down_sync(0xffffffffu, s, off);
    if (threadIdx.x == 0) out[row] = s;
}

// ---------------- cost GEMM (R1 single-buffered body) ----------------
// Cout[i][j] = clip(a2[i]+b2[j]-2*dot,0,1e6)*KSCALE
// SYM: A==B, triangular linearized grid, mirror-writes transpose tile.
#define GBM 128
#define GBN 128
#define GBK 8
#define NT 32               // N / GBM tile count
#define NTRI (NT * (NT + 1) / 2)   // 528

template <bool SYM>
__global__ __launch_bounds__(256) void gemm_cost_kernel(
    const float* __restrict__ A, const float* __restrict__ B,
    const float* __restrict__ a2, const float* __restrict__ b2,
    float* __restrict__ Cout)
{
    int bx, by;
    if (SYM) {
        // decode linear idx -> (by, bx) with bx >= by
        int idx = blockIdx.x;
        float disc = (float)((2 * NT + 1) * (2 * NT + 1) - 8 * idx);
        int b = (int)((2 * NT + 1 - sqrtf(disc)) * 0.5f);
        // fixup (off(b) = b*NT - b*(b-1)/2)
        #pragma unroll 1
        while (b > 0 && b * NT - b * (b - 1) / 2 > idx) b--;
        #pragma unroll 1
        while ((b + 1) * NT - (b + 1) * b / 2 <= idx) b++;
        by = b;
        bx = by + (idx - (b * NT - b * (b - 1) / 2));
    } else {
        bx = blockIdx.x;
        by = blockIdx.y;
    }

    __shared__ float As[GBK][GBM];
    __shared__ float Bs[GBK][GBN];
    const int tid  = threadIdx.x;
    const int irow = tid >> 1;
    const int icol = (tid & 1) * 4;
    const int trow = (tid >> 4) * 8;
    const int tcol = (tid & 15) * 8;

    const float* Aptr = A + (size_t)(by * GBM + irow) * D + icol;
    const float* Bptr = B + (size_t)(bx * GBN + irow) * D + icol;

    float acc[8][8];
    #pragma unroll
    for (int i = 0; i < 8; i++)
        #pragma unroll
        for (int j = 0; j < 8; j++) acc[i][j] = 0.f;

    for (int k0 = 0; k0 < D; k0 += GBK) {
        float4 av = *(const float4*)(Aptr + k0);
        float4 bv = *(const float4*)(Bptr + k0);
        __syncthreads();
        As[icol + 0][irow] = av.x; As[icol + 1][irow] = av.y;
        As[icol + 2][irow] = av.z; As[icol + 3][irow] = av.w;
        Bs[icol + 0][irow] = bv.x; Bs[icol + 1][irow] = bv.y;
        Bs[icol + 2][irow] = bv.z; Bs[icol + 3][irow] = bv.w;
        __syncthreads();
        #pragma unroll
        for (int k = 0; k < GBK; k++) {
            float ar[8], br[8];
            #pragma unroll
            for (int i = 0; i < 8; i++) ar[i] = As[k][trow + i];
            #pragma unroll
            for (int j = 0; j < 8; j++) br[j] = Bs[k][tcol + j];
            #pragma unroll
            for (int i = 0; i < 8; i++)
                #pragma unroll
                for (int j = 0; j < 8; j++)
                    acc[i][j] = fmaf(ar[i], br[j], acc[i][j]);
        }
    }

    const int gi = by * GBM + trow;
    const int gj = bx * GBN + tcol;

    #pragma unroll
    for (int i = 0; i < 8; i++) {
        float ai = __ldg(a2 + gi + i);
        #pragma unroll
        for (int j = 0; j < 8; j++) {
            float c = ai + __ldg(b2 + gj + j) - 2.0f * acc[i][j];
            c = fminf(fmaxf(c, 0.0f), 1.0e6f);
            acc[i][j] = c * KSCALE;
        }
    }

    #pragma unroll
    for (int i = 0; i < 8; i++) {
        float* crow = Cout + (size_t)(gi + i) * N + gj;
        #pragma unroll
        for (int j = 0; j < 8; j++) crow[j] = acc[i][j];
    }

    if (SYM && bx != by) {
        #pragma unroll
        for (int j = 0; j < 8; j++) {
            float* crow = Cout + (size_t)(gj + j) * N + gi;
            #pragma unroll
            for (int i = 0; i < 8; i++) crow[i] = acc[i][j];
        }
    }
}

// ---------------- transpose (Cyx = Cxy^T) ----------------
__global__ void transpose_kernel(const float* __restrict__ in, float* __restrict__ out) {
    __shared__ float tile[32][33];
    int x = blockIdx.x * 32 + threadIdx.x;
    int y = blockIdx.y * 32 + threadIdx.y;
    #pragma unroll
    for (int r = 0; r < 32; r += 8)
        tile[threadIdx.y + r][threadIdx.x] = in[(size_t)(y + r) * N + x];
    __syncthreads();
    int xo = blockIdx.y * 32 + threadIdx.x;
    int yo = blockIdx.x * 32 + threadIdx.y;
    #pragma unroll
    for (int r = 0; r < 32; r += 8)
        out[(size_t)(yo + r) * N + xo] = tile[threadIdx.x][threadIdx.y + r];
}

// ---------------- potential init ----------------
__global__ void init_pot_kernel() {
    int i = blockIdx.x * 256 + threadIdx.x;
    if (i < 3 * N) {
        (&d_F[0][0])[i] = 0.f;
        (&d_G[0][0])[i] = 0.f;
    }
}

// ---------------- matrix select helper ----------------
__device__ __forceinline__ const float* pick_matrix(int p, int phase) {
    if (p == 0) return (phase == 0) ? d_Cxy : d_Cyx;
    if (p == 1) return d_Cxx;
    return d_Cyy;
}

// ---------------- robust half-iteration (online max LSE), writes L ----------
__device__ __forceinline__ void lse_up(float& m, float& s, float a) {
    if (a <= m) {
        s += ex2f(a - m);
    } else {
        s = fmaf(s, ex2f(m - a), 1.0f);
        m = a;
    }
}

__global__ __launch_bounds__(256) void lse_robust_kernel(int phase) {
    const int p = blockIdx.y;
    const float* M = pick_matrix(p, phase);
    const float* vin = (phase == 0) ? d_G[p] : d_F[p];
    float* vout      = (phase == 0) ? d_F[p] : d_G[p];

    const int row = blockIdx.x;
    const float* Mr = M + (size_t)row * N;
    const int t4 = threadIdx.x * 4;

    float m = __int_as_float(0xff800000);
    float s = 0.f;
    #pragma unroll
    for (int k = 0; k < 4; k++) {
        int j = t4 + k * 1024;
        float4 mv = *(const float4*)(Mr + j);
        float4 vv = *(const float4*)(vin + j);
        lse_up(m, s, vv.x - mv.x);
        lse_up(m, s, vv.y - mv.y);
        lse_up(m, s, vv.z - mv.z);
        lse_up(m, s, vv.w - mv.w);
    }

    __shared__ float sm[256], ss[256];
    sm[threadIdx.x] = m;
    ss[threadIdx.x] = s;
    __syncthreads();
    for (int off = 128; off > 0; off >>= 1) {
        if (threadIdx.x < off) {
            float m1 = sm[threadIdx.x], s1 = ss[threadIdx.x];
            float m2 = sm[threadIdx.x + off], s2 = ss[threadIdx.x + off];
            float mm = fmaxf(m1, m2);
            sm[threadIdx.x] = mm;
            ss[threadIdx.x] = fmaf(s1, ex2f(m1 - mm), s2 * ex2f(m2 - mm));
        }
        __syncthreads();
    }
    if (threadIdx.x == 0) {
        float L = sm[0] + log2f(ss[0]);
        vout[row] = 12.0f - L;
        d_L[phase][p][row] = L;
    }
}

// ---------------- fast half-iteration: 4 rows/block, shifted, branch-free ----
#define RPB 4

template <bool STREAM>
__device__ __forceinline__ void fast_rows(
    const float* __restrict__ M, int row0, int t4,
    const float4* __restrict__ vv, const float* __restrict__ Lp, float* s)
{
    #pragma unroll
    for (int r = 0; r < RPB; r++) {
        const float* Mr = M + (size_t)(row0 + r) * N;
        float acc = 0.f;
        #pragma unroll
        for (int k = 0; k < 4; k++) {
            const float4* mp = (const float4*)(Mr + t4 + k * 1024);
            float4 mv = STREAM ? __ldcs(mp) : __ldg(mp);
            float e0 = ex2f((vv[k].x - Lp[r]) - mv.x);
            float e1 = ex2f((vv[k].y - Lp[r]) - mv.y);
            float e2 = ex2f((vv[k].z - Lp[r]) - mv.z);
            float e3 = ex2f((vv[k].w - Lp[r]) - mv.w);
            acc += (e0 + e1) + (e2 + e3);
        }
        s[r] = acc;
    }
}

__global__ __launch_bounds__(256) void lse_fast_kernel(int phase) {
    const int p = blockIdx.y;   // 0=xy, 1=xx, 2=yy
    const float* M = pick_matrix(p, phase);
    const float* vin = (phase == 0) ? d_G[p] : d_F[p];
    float* vout      = (phase == 0) ? d_F[p] : d_G[p];

    const int row0 = blockIdx.x * RPB;
    const int t4 = threadIdx.x * 4;

    float4 vv[4];
    #pragma unroll
    for (int k = 0; k < 4; k++)
        vv[k] = __ldg((const float4*)(vin + t4 + k * 1024));

    float Lp[RPB];
    #pragma unroll
    for (int r = 0; r < RPB; r++)
        Lp[r] = d_L[phase][p][row0 + r];

    float s[RPB];
    if (p == 0) fast_rows<true >(M, row0, t4, vv, Lp, s);
    else        fast_rows<false>(M, row0, t4, vv, Lp, s);

    // reduce 4 row-sums simultaneously
    #pragma unroll
    for (int off = 16; off > 0; off >>= 1) {
        #pragma unroll
        for (int r = 0; r < RPB; r++)
            s[r] += __shfl_down_sync(0xffffffffu, s[r], off);
    }
    __shared__ float sw[RPB][8];
    const int lane = threadIdx.x & 31;
    const int wid  = threadIdx.x >> 5;
    if (lane == 0) {
        #pragma unroll
        for (int r = 0; r < RPB; r++) sw[r][wid] = s[r];
    }
    __syncthreads();
    if (threadIdx.x < RPB) {
        const int r = threadIdx.x;
        float S = 0.f;
        #pragma unroll
        for (int w = 0; w < 8; w++) S += sw[r][w];
        float Lnew = Lp[r] + log2f(S);
        vout[row0 + r] = 12.0f - Lnew;
        d_L[phase][p][row0 + r] = Lnew;
    }
}

// ---------------- final scalar reduce ----------------
__global__ __launch_bounds__(256) void final_reduce_kernel(float* __restrict__ out) {
    __shared__ double sh[3][256];
    const int tid = threadIdx.x;
    double acc0 = 0.0, acc1 = 0.0, acc2 = 0.0;
    for (int j = tid; j < N; j += 256) {
        acc0 += (double)d_F[0][j] + (double)d_G[0][j];
        acc1 += (double)d_F[1][j] + (double)d_G[1][j];
        acc2 += (double)d_F[2][j] + (double)d_G[2][j];
    }
    sh[0][tid] = acc0; sh[1][tid] = acc1; sh[2][tid] = acc2;
    __syncthreads();
    for (int off = 128; off > 0; off >>= 1) {
        if (tid < off) {
            sh[0][tid] += sh[0][tid + off];
            sh[1][tid] += sh[1][tid + off];
            sh[2][tid] += sh[2][tid + off];
        }
        __syncthreads();
    }
    if (tid == 0) {
        double Sdiff = sh[0][0] - 0.5 * (sh[1][0] + sh[2][0]);
        double val = Sdiff * OUT_SCALE;
        out[0] = (float)(val > 0.0 ? val : 0.0);
    }
}

// ---------------- launch ----------------
extern "C" void kernel_launch(void* const* d_in, const int* in_sizes, int n_in,
                              void* d_out, int out_size)
{
    const float* x = (const float*)d_in[0];
    const float* y = (const float*)d_in[1];
    float* out = (float*)d_out;

    float *Cxy, *Cyx, *Cxx, *Cyy, *xsq, *ysq;
    cudaGetSymbolAddress((void**)&Cxy, d_Cxy);
    cudaGetSymbolAddress((void**)&Cyx, d_Cyx);
    cudaGetSymbolAddress((void**)&Cxx, d_Cxx);
    cudaGetSymbolAddress((void**)&Cyy, d_Cyy);
    cudaGetSymbolAddress((void**)&xsq, d_xsq);
    cudaGetSymbolAddress((void**)&ysq, d_ysq);

    dim3 rsBlock(32, 8);
    rowsq_kernel<<<N / 8, rsBlock>>>(x, xsq);
    rowsq_kernel<<<N / 8, rsBlock>>>(y, ysq);

    dim3 gGrid(N / GBN, N / GBM);
    gemm_cost_kernel<false><<<gGrid, 256>>>(x, y, xsq, ysq, Cxy);
    gemm_cost_kernel<true ><<<NTRI, 256>>>(x, x, xsq, xsq, Cxx);
    gemm_cost_kernel<true ><<<NTRI, 256>>>(y, y, ysq, ysq, Cyy);

    dim3 tBlock(32, 8);
    dim3 tGrid(N / 32, N / 32);
    transpose_kernel<<<tGrid, tBlock>>>(Cxy, Cyx);

    init_pot_kernel<<<(3 * N + 255) / 256, 256>>>();

    dim3 rGrid(N, 3);
    dim3 fGrid(N / RPB, 3);
    const int WARMUP = 3;
    for (int it = 0; it < WARMUP; it++) {
        lse_robust_kernel<<<rGrid, 256>>>(0);
        lse_robust_kernel<<<rGrid, 256>>>(1);
    }
    for (int it = WARMUP; it < 50; it++) {
        lse_fast_kernel<<<fGrid, 256>>>(0);
        lse_fast_kernel<<<fGrid, 256>>>(1);
    }

    final_reduce_kernel<<<1, 256>>>(out);
}

// round 5
// speedup vs baseline: 1.5008x; 1.1545x over previous
#include <cuda_runtime.h>
#include <cuda_bf16.h>
#include <math.h>
#include <cstdint>

#define N 4096
#define D 512
#define NN (N * N)

// log2-domain scale: (1/EPS) * log2(e)
#define KSCALE 14.4269504088896340736f
// EPS * ln2 / N
#define OUT_SCALE (0.1 * 0.69314718055994530942 / 4096.0)

// ---------------- device scratch (no allocations allowed) ----------------
__device__ float d_Cxy[NN];
__device__ float d_Cyx[NN];
__device__ float d_Cxx[NN];
__device__ float d_Cyy[NN];
__device__ float d_xsq[N];
__device__ float d_ysq[N];
__device__ float d_F[3][N];
__device__ float d_G[3][N];
__device__ float d_L[2][3][N];
__device__ __nv_bfloat16 d_xhi[N * D];
__device__ __nv_bfloat16 d_xlo[N * D];
__device__ __nv_bfloat16 d_yhi[N * D];
__device__ __nv_bfloat16 d_ylo[N * D];

__device__ __forceinline__ float ex2f(float x) {
    float y;
    asm("ex2.approx.ftz.f32 %0, %1;" : "=f"(y) : "f"(x));
    return y;
}

// ---------------- bf16 split conversion ----------------
__global__ void convert_kernel(const float* __restrict__ X,
                               __nv_bfloat16* __restrict__ hi,
                               __nv_bfloat16* __restrict__ lo) {
    int i = blockIdx.x * 256 + threadIdx.x;
    float v = X[i];
    __nv_bfloat16 h = __float2bfloat16_rn(v);
    float r = v - __bfloat162float(h);
    hi[i] = h;
    lo[i] = __float2bfloat16_rn(r);
}

// ---------------- row sum-of-squares (fp32 exact) ----------------
__global__ void rowsq_kernel(const float* __restrict__ X, float* __restrict__ out) {
    int row = blockIdx.x * 8 + threadIdx.y;
    const float* xr = X + (size_t)row * D;
    float s = 0.f;
    for (int k = threadIdx.x; k < D; k += 32) {
        float v = __ldg(xr + k);
        s = fmaf(v, v, s);
    }
    #pragma unroll
    for (int off = 16; off > 0; off >>= 1)
        s += __shfl_down_sync(0xffffffffu, s, off);
    if (threadIdx.x == 0) out[row] = s;
}

// ---------------- HMMA split-bf16 cost GEMM ----------------
// Cout[i][j] = clip(a2[i]+b2[j]-2*(hi.hi + hi.lo + lo.hi), 0, 1e6) * KSCALE
#define NT 32
#define NTRI (NT * (NT + 1) / 2)   // 528
#define KC 32                      // k per smem stage
#define SROW 40                    // padded smem row (bf16 elems): conflict-free

__device__ __forceinline__ void mma_bf16(float* c, const uint32_t* a, const uint32_t* b) {
    asm volatile(
        "mma.sync.aligned.m16n8k16.row.col.f32.bf16.bf16.f32 "
        "{%0,%1,%2,%3}, {%4,%5,%6,%7}, {%8,%9}, {%0,%1,%2,%3};"
        : "+f"(c[0]), "+f"(c[1]), "+f"(c[2]), "+f"(c[3])
        : "r"(a[0]), "r"(a[1]), "r"(a[2]), "r"(a[3]), "r"(b[0]), "r"(b[1]));
}

template <bool SYM, bool WRITE_T>
__global__ __launch_bounds__(256) void tc_gemm_kernel(
    const __nv_bfloat16* __restrict__ Ahi, const __nv_bfloat16* __restrict__ Alo,
    const __nv_bfloat16* __restrict__ Bhi, const __nv_bfloat16* __restrict__ Blo,
    const float* __restrict__ a2, const float* __restrict__ b2,
    float* __restrict__ Cout, float* __restrict__ CoutT)
{
    int bx, by;
    if (SYM) {
        int idx = blockIdx.x;
        float disc = (float)((2 * NT + 1) * (2 * NT + 1) - 8 * idx);
        int b = (int)((2 * NT + 1 - sqrtf(disc)) * 0.5f);
        #pragma unroll 1
        while (b > 0 && b * NT - b * (b - 1) / 2 > idx) b--;
        #pragma unroll 1
        while ((b + 1) * NT - (b + 1) * b / 2 <= idx) b++;
        by = b;
        bx = by + (idx - (b * NT - b * (b - 1) / 2));
    } else {
        bx = blockIdx.x & (NT - 1);
        by = blockIdx.x >> 5;
    }

    __shared__ __align__(16) __nv_bfloat16 sAhi[128 * SROW];
    __shared__ __align__(16) __nv_bfloat16 sAlo[128 * SROW];
    __shared__ __align__(16) __nv_bfloat16 sBhi[128 * SROW];
    __shared__ __align__(16) __nv_bfloat16 sBlo[128 * SROW];

    const int tid = threadIdx.x;
    const int wid = tid >> 5;
    const int lane = tid & 31;
    const int g = lane >> 2;        // 0..7
    const int tg = lane & 3;        // 0..3
    const int wm = wid & 3;         // warp row (32 rows each)
    const int wn = wid >> 2;        // warp col (64 cols each)

    const int rowA = by * 128;
    const int rowB = bx * 128;

    float acc[2][8][4];
    #pragma unroll
    for (int mf = 0; mf < 2; mf++)
        #pragma unroll
        for (int nf = 0; nf < 8; nf++)
            #pragma unroll
            for (int q = 0; q < 4; q++) acc[mf][nf][q] = 0.f;

    const int lrow = tid >> 2;      // 0..63? no: tid>>2 in 0..63 — need 0..127
    // load mapping: u = tid + it*256, row = u>>2 (0..127), seg = u&3

    for (int k0 = 0; k0 < D; k0 += KC) {
        __syncthreads();
        #pragma unroll
        for (int it = 0; it < 2; it++) {
            int u = tid + it * 256;
            int r = u >> 2;
            int seg = u & 3;
            const size_t goff = (size_t)r * D + k0 + seg * 8;
            const int soff = r * SROW + seg * 8;
            *(float4*)(sAhi + soff) = __ldg((const float4*)(Ahi + (size_t)rowA * D + goff));
            *(float4*)(sAlo + soff) = __ldg((const float4*)(Alo + (size_t)rowA * D + goff));
            *(float4*)(sBhi + soff) = __ldg((const float4*)(Bhi + (size_t)rowB * D + goff));
            *(float4*)(sBlo + soff) = __ldg((const float4*)(Blo + (size_t)rowB * D + goff));
        }
        __syncthreads();

        #pragma unroll
        for (int ks = 0; ks < 2; ks++) {
            const int kb = ks * 16;
            // A fragments (hi & lo) for both 16-row m-frags
            uint32_t ah[2][4], al[2][4];
            #pragma unroll
            for (int mf = 0; mf < 2; mf++) {
                const int r0 = wm * 32 + mf * 16 + g;
                const int c0 = kb + tg * 2;
                ah[mf][0] = *(const uint32_t*)(sAhi + r0 * SROW + c0);
                ah[mf][1] = *(const uint32_t*)(sAhi + (r0 + 8) * SROW + c0);
                ah[mf][2] = *(const uint32_t*)(sAhi + r0 * SROW + c0 + 8);
                ah[mf][3] = *(const uint32_t*)(sAhi + (r0 + 8) * SROW + c0 + 8);
                al[mf][0] = *(const uint32_t*)(sAlo + r0 * SROW + c0);
                al[mf][1] = *(const uint32_t*)(sAlo + (r0 + 8) * SROW + c0);
                al[mf][2] = *(const uint32_t*)(sAlo + r0 * SROW + c0 + 8);
                al[mf][3] = *(const uint32_t*)(sAlo + (r0 + 8) * SROW + c0 + 8);
            }
            #pragma unroll
            for (int nf = 0; nf < 8; nf++) {
                const int n0 = wn * 64 + nf * 8 + g;
                const int c0 = kb + tg * 2;
                uint32_t bh[2], bl[2];
                bh[0] = *(const uint32_t*)(sBhi + n0 * SROW + c0);
                bh[1] = *(const uint32_t*)(sBhi + n0 * SROW + c0 + 8);
                bl[0] = *(const uint32_t*)(sBlo + n0 * SROW + c0);
                bl[1] = *(const uint32_t*)(sBlo + n0 * SROW + c0 + 8);
                #pragma unroll
                for (int mf = 0; mf < 2; mf++) {
                    mma_bf16(acc[mf][nf], ah[mf], bh);
                    mma_bf16(acc[mf][nf], ah[mf], bl);
                    mma_bf16(acc[mf][nf], al[mf], bh);
                }
            }
        }
    }

    // ---------------- epilogue ----------------
    #pragma unroll
    for (int mf = 0; mf < 2; mf++) {
        const int r0 = by * 128 + wm * 32 + mf * 16 + g;
        const int r1 = r0 + 8;
        const float a20 = __ldg(a2 + r0);
        const float a21 = __ldg(a2 + r1);
        #pragma unroll
        for (int nf = 0; nf < 8; nf++) {
            const int c0 = bx * 128 + wn * 64 + nf * 8 + tg * 2;
            const float b20 = __ldg(b2 + c0);
            const float b21 = __ldg(b2 + c0 + 1);
            float v00 = fminf(fmaxf(a20 + b20 - 2.0f * acc[mf][nf][0], 0.f), 1.0e6f) * KSCALE;
            float v01 = fminf(fmaxf(a20 + b21 - 2.0f * acc[mf][nf][1], 0.f), 1.0e6f) * KSCALE;
            float v10 = fminf(fmaxf(a21 + b20 - 2.0f * acc[mf][nf][2], 0.f), 1.0e6f) * KSCALE;
            float v11 = fminf(fmaxf(a21 + b21 - 2.0f * acc[mf][nf][3], 0.f), 1.0e6f) * KSCALE;

            *(float2*)(Cout + (size_t)r0 * N + c0) = make_float2(v00, v01);
            *(float2*)(Cout + (size_t)r1 * N + c0) = make_float2(v10, v11);

            if (WRITE_T) {
                float* t0 = CoutT + (size_t)c0 * N;
                float* t1 = CoutT + (size_t)(c0 + 1) * N;
                t0[r0] = v00; t0[r1] = v10;
                t1[r0] = v01; t1[r1] = v11;
            }
            if (SYM && bx != by) {
                float* t0 = Cout + (size_t)c0 * N;
                float* t1 = Cout + (size_t)(c0 + 1) * N;
                t0[r0] = v00; t0[r1] = v10;
                t1[r0] = v01; t1[r1] = v11;
            }
        }
    }
}

// ---------------- potential init ----------------
__global__ void init_pot_kernel() {
    int i = blockIdx.x * 256 + threadIdx.x;
    if (i < 3 * N) {
        (&d_F[0][0])[i] = 0.f;
        (&d_G[0][0])[i] = 0.f;
    }
}

// ---------------- matrix select helper ----------------
__device__ __forceinline__ const float* pick_matrix(int p, int phase) {
    if (p == 0) return (phase == 0) ? d_Cxy : d_Cyx;
    if (p == 1) return d_Cxx;
    return d_Cyy;
}

// ---------------- robust half-iteration (online max LSE), writes L ----------
__device__ __forceinline__ void lse_up(float& m, float& s, float a) {
    if (a <= m) {
        s += ex2f(a - m);
    } else {
        s = fmaf(s, ex2f(m - a), 1.0f);
        m = a;
    }
}

__global__ __launch_bounds__(256) void lse_robust_kernel(int phase) {
    const int p = blockIdx.y;
    const float* M = pick_matrix(p, phase);
    const float* vin = (phase == 0) ? d_G[p] : d_F[p];
    float* vout      = (phase == 0) ? d_F[p] : d_G[p];

    const int row = blockIdx.x;
    const float* Mr = M + (size_t)row * N;
    const int t4 = threadIdx.x * 4;

    float m = __int_as_float(0xff800000);
    float s = 0.f;
    #pragma unroll
    for (int k = 0; k < 4; k++) {
        int j = t4 + k * 1024;
        float4 mv = *(const float4*)(Mr + j);
        float4 vv = *(const float4*)(vin + j);
        lse_up(m, s, vv.x - mv.x);
        lse_up(m, s, vv.y - mv.y);
        lse_up(m, s, vv.z - mv.z);
        lse_up(m, s, vv.w - mv.w);
    }

    __shared__ float sm[256], ss[256];
    sm[threadIdx.x] = m;
    ss[threadIdx.x] = s;
    __syncthreads();
    for (int off = 128; off > 0; off >>= 1) {
        if (threadIdx.x < off) {
            float m1 = sm[threadIdx.x], s1 = ss[threadIdx.x];
            float m2 = sm[threadIdx.x + off], s2 = ss[threadIdx.x + off];
            float mm = fmaxf(m1, m2);
            sm[threadIdx.x] = mm;
            ss[threadIdx.x] = fmaf(s1, ex2f(m1 - mm), s2 * ex2f(m2 - mm));
        }
        __syncthreads();
    }
    if (threadIdx.x == 0) {
        float L = sm[0] + log2f(ss[0]);
        vout[row] = 12.0f - L;
        d_L[phase][p][row] = L;
    }
}

// ---------------- fast half-iteration: 4 rows/block, shifted, branch-free ----
#define RPB 4

template <bool STREAM>
__device__ __forceinline__ void fast_rows(
    const float* __restrict__ M, int row0, int t4,
    const float4* __restrict__ vv, const float* __restrict__ Lp, float* s)
{
    #pragma unroll
    for (int r = 0; r < RPB; r++) {
        const float* Mr = M + (size_t)(row0 + r) * N;
        float acc = 0.f;
        #pragma unroll
        for (int k = 0; k < 4; k++) {
            const float4* mp = (const float4*)(Mr + t4 + k * 1024);
            float4 mv = STREAM ? __ldcs(mp) : __ldg(mp);
            float e0 = ex2f((vv[k].x - Lp[r]) - mv.x);
            float e1 = ex2f((vv[k].y - Lp[r]) - mv.y);
            float e2 = ex2f((vv[k].z - Lp[r]) - mv.z);
            float e3 = ex2f((vv[k].w - Lp[r]) - mv.w);
            acc += (e0 + e1) + (e2 + e3);
        }
        s[r] = acc;
    }
}

__global__ __launch_bounds__(256) void lse_fast_kernel(int phase) {
    const int p = blockIdx.y;
    const float* M = pick_matrix(p, phase);
    const float* vin = (phase == 0) ? d_G[p] : d_F[p];
    float* vout      = (phase == 0) ? d_F[p] : d_G[p];

    const int row0 = blockIdx.x * RPB;
    const int t4 = threadIdx.x * 4;

    float4 vv[4];
    #pragma unroll
    for (int k = 0; k < 4; k++)
        vv[k] = __ldg((const float4*)(vin + t4 + k * 1024));

    float Lp[RPB];
    #pragma unroll
    for (int r = 0; r < RPB; r++)
        Lp[r] = d_L[phase][p][row0 + r];

    float s[RPB];
    if (p == 0) fast_rows<true >(M, row0, t4, vv, Lp, s);
    else        fast_rows<false>(M, row0, t4, vv, Lp, s);

    #pragma unroll
    for (int off = 16; off > 0; off >>= 1) {
        #pragma unroll
        for (int r = 0; r < RPB; r++)
            s[r] += __shfl_down_sync(0xffffffffu, s[r], off);
    }
    __shared__ float sw[RPB][8];
    const int lane = threadIdx.x & 31;
    const int wid  = threadIdx.x >> 5;
    if (lane == 0) {
        #pragma unroll
        for (int r = 0; r < RPB; r++) sw[r][wid] = s[r];
    }
    __syncthreads();
    if (threadIdx.x < RPB) {
        const int r = threadIdx.x;
        float S = 0.f;
        #pragma unroll
        for (int w = 0; w < 8; w++) S += sw[r][w];
        float Lnew = Lp[r] + log2f(S);
        vout[row0 + r] = 12.0f - Lnew;
        d_L[phase][p][row0 + r] = Lnew;
    }
}

// ---------------- final scalar reduce ----------------
__global__ __launch_bounds__(256) void final_reduce_kernel(float* __restrict__ out) {
    __shared__ double sh[3][256];
    const int tid = threadIdx.x;
    double acc0 = 0.0, acc1 = 0.0, acc2 = 0.0;
    for (int j = tid; j < N; j += 256) {
        acc0 += (double)d_F[0][j] + (double)d_G[0][j];
        acc1 += (double)d_F[1][j] + (double)d_G[1][j];
        acc2 += (double)d_F[2][j] + (double)d_G[2][j];
    }
    sh[0][tid] = acc0; sh[1][tid] = acc1; sh[2][tid] = acc2;
    __syncthreads();
    for (int off = 128; off > 0; off >>= 1) {
        if (tid < off) {
            sh[0][tid] += sh[0][tid + off];
            sh[1][tid] += sh[1][tid + off];
            sh[2][tid] += sh[2][tid + off];
        }
        __syncthreads();
    }
    if (tid == 0) {
        double Sdiff = sh[0][0] - 0.5 * (sh[1][0] + sh[2][0]);
        double val = Sdiff * OUT_SCALE;
        out[0] = (float)(val > 0.0 ? val : 0.0);
    }
}

// ---------------- launch ----------------
extern "C" void kernel_launch(void* const* d_in, const int* in_sizes, int n_in,
                              void* d_out, int out_size)
{
    const float* x = (const float*)d_in[0];
    const float* y = (const float*)d_in[1];
    float* out = (float*)d_out;

    float *Cxy, *Cyx, *Cxx, *Cyy, *xsq, *ysq;
    __nv_bfloat16 *xhi, *xlo, *yhi, *ylo;
    cudaGetSymbolAddress((void**)&Cxy, d_Cxy);
    cudaGetSymbolAddress((void**)&Cyx, d_Cyx);
    cudaGetSymbolAddress((void**)&Cxx, d_Cxx);
    cudaGetSymbolAddress((void**)&Cyy, d_Cyy);
    cudaGetSymbolAddress((void**)&xsq, d_xsq);
    cudaGetSymbolAddress((void**)&ysq, d_ysq);
    cudaGetSymbolAddress((void**)&xhi, d_xhi);
    cudaGetSymbolAddress((void**)&xlo, d_xlo);
    cudaGetSymbolAddress((void**)&yhi, d_yhi);
    cudaGetSymbolAddress((void**)&ylo, d_ylo);

    convert_kernel<<<(N * D) / 256, 256>>>(x, xhi, xlo);
    convert_kernel<<<(N * D) / 256, 256>>>(y, yhi, ylo);

    dim3 rsBlock(32, 8);
    rowsq_kernel<<<N / 8, rsBlock>>>(x, xsq);
    rowsq_kernel<<<N / 8, rsBlock>>>(y, ysq);

    tc_gemm_kernel<false, true><<<NT * NT, 256>>>(
        xhi, xlo, yhi, ylo, xsq, ysq, Cxy, Cyx);
    tc_gemm_kernel<true, false><<<NTRI, 256>>>(
        xhi, xlo, xhi, xlo, xsq, xsq, Cxx, nullptr);
    tc_gemm_kernel<true, false><<<NTRI, 256>>>(
        yhi, ylo, yhi, ylo, ysq, ysq, Cyy, nullptr);

    init_pot_kernel<<<(3 * N + 255) / 256, 256>>>();

    dim3 rGrid(N, 3);
    dim3 fGrid(N / RPB, 3);
    const int WARMUP = 3;
    for (int it = 0; it < WARMUP; it++) {
        lse_robust_kernel<<<rGrid, 256>>>(0);
        lse_robust_kernel<<<rGrid, 256>>>(1);
    }
    for (int it = WARMUP; it < 50; it++) {
        lse_fast_kernel<<<fGrid, 256>>>(0);
        lse_fast_kernel<<<fGrid, 256>>>(1);
    }

    final_reduce_kernel<<<1, 256>>>(out);
}

// round 8
// speedup vs baseline: 2.3547x; 1.5690x over previous
#include <cuda_runtime.h>
#include <cuda_bf16.h>
#include <cuda_fp16.h>
#include <math.h>
#include <cstdint>

#define N 4096
#define D 512
#define NN (N * N)

// log2-domain scale: (1/EPS) * log2(e)
#define KSCALE 14.4269504088896340736f
// EPS * ln2 / N
#define OUT_SCALE (0.1 * 0.69314718055994530942 / 4096.0)

// ---------------- device scratch (no allocations allowed) ----------------
__device__ __half d_ChXY[NN];
__device__ __half d_ChYX[NN];
__device__ __half d_ChXX[NN];
__device__ __half d_ChYY[NN];
__device__ float d_Ctmp[NN];
__device__ int   d_rmin[4][N];    // float bits; 0=xy rows,1=xy cols(yx rows),2=xx,3=yy
__device__ float d_xsq[N];
__device__ float d_ysq[N];
__device__ float d_F[3][N];
__device__ float d_G[3][N];
__device__ float d_L[2][3][N];
__device__ __nv_bfloat16 d_xhi[N * D];
__device__ __nv_bfloat16 d_xlo[N * D];
__device__ __nv_bfloat16 d_yhi[N * D];
__device__ __nv_bfloat16 d_ylo[N * D];

__device__ __forceinline__ float ex2f(float x) {
    float y;
    asm("ex2.approx.ftz.f32 %0, %1;" : "=f"(y) : "f"(x));
    return y;
}

// ---------------- bf16 split conversion ----------------
__global__ void convert_kernel(const float* __restrict__ X,
                               __nv_bfloat16* __restrict__ hi,
                               __nv_bfloat16* __restrict__ lo) {
    int i = blockIdx.x * 256 + threadIdx.x;
    float v = X[i];
    __nv_bfloat16 h = __float2bfloat16_rn(v);
    float r = v - __bfloat162float(h);
    hi[i] = h;
    lo[i] = __float2bfloat16_rn(r);
}

// ---------------- row sum-of-squares (fp32 exact) ----------------
__global__ void rowsq_kernel(const float* __restrict__ X, float* __restrict__ out) {
    int row = blockIdx.x * 8 + threadIdx.y;
    const float* xr = X + (size_t)row * D;
    float s = 0.f;
    for (int k = threadIdx.x; k < D; k += 32) {
        float v = __ldg(xr + k);
        s = fmaf(v, v, s);
    }
    #pragma unroll
    for (int off = 16; off > 0; off >>= 1)
        s += __shfl_down_sync(0xffffffffu, s, off);
    if (threadIdx.x == 0) out[row] = s;
}

// ---------------- init min arrays ----------------
__global__ void init_min_kernel() {
    int i = blockIdx.x * 256 + threadIdx.x;
    if (i < 4 * N) (&d_rmin[0][0])[i] = 0x7F7FFFFF;   // max finite float
}

// ---------------- HMMA split-bf16 cost GEMM (+ row/col min) ----------------
#define NT 32
#define NTRI (NT * (NT + 1) / 2)   // 528
#define KC 32
#define SROW 40

__device__ __forceinline__ void mma_bf16(float* c, const uint32_t* a, const uint32_t* b) {
    asm volatile(
        "mma.sync.aligned.m16n8k16.row.col.f32.bf16.bf16.f32 "
        "{%0,%1,%2,%3}, {%4,%5,%6,%7}, {%8,%9}, {%0,%1,%2,%3};"
        : "+f"(c[0]), "+f"(c[1]), "+f"(c[2]), "+f"(c[3])
        : "r"(a[0]), "r"(a[1]), "r"(a[2]), "r"(a[3]), "r"(b[0]), "r"(b[1]));
}

template <bool SYM>
__global__ __launch_bounds__(256) void tc_gemm_kernel(
    const __nv_bfloat16* __restrict__ Ahi, const __nv_bfloat16* __restrict__ Alo,
    const __nv_bfloat16* __restrict__ Bhi, const __nv_bfloat16* __restrict__ Blo,
    const float* __restrict__ a2, const float* __restrict__ b2,
    float* __restrict__ Cout, int* __restrict__ rminArr, int* __restrict__ cminArr)
{
    int bx, by;
    if (SYM) {
        int idx = blockIdx.x;
        float disc = (float)((2 * NT + 1) * (2 * NT + 1) - 8 * idx);
        int b = (int)((2 * NT + 1 - sqrtf(disc)) * 0.5f);
        #pragma unroll 1
        while (b > 0 && b * NT - b * (b - 1) / 2 > idx) b--;
        #pragma unroll 1
        while ((b + 1) * NT - (b + 1) * b / 2 <= idx) b++;
        by = b;
        bx = by + (idx - (b * NT - b * (b - 1) / 2));
    } else {
        bx = blockIdx.x & (NT - 1);
        by = blockIdx.x >> 5;
    }

    __shared__ __align__(16) __nv_bfloat16 sAhi[128 * SROW];
    __shared__ __align__(16) __nv_bfloat16 sAlo[128 * SROW];
    __shared__ __align__(16) __nv_bfloat16 sBhi[128 * SROW];
    __shared__ __align__(16) __nv_bfloat16 sBlo[128 * SROW];
    __shared__ int sRmin[128], sCmin[128];

    const int tid = threadIdx.x;
    const int wid = tid >> 5;
    const int lane = tid & 31;
    const int g = lane >> 2;
    const int tg = lane & 3;
    const int wm = wid & 3;
    const int wn = wid >> 2;

    if (tid < 128) { sRmin[tid] = 0x7F7FFFFF; sCmin[tid] = 0x7F7FFFFF; }

    const int rowA = by * 128;
    const int rowB = bx * 128;

    float acc[2][8][4];
    #pragma unroll
    for (int mf = 0; mf < 2; mf++)
        #pragma unroll
        for (int nf = 0; nf < 8; nf++)
            #pragma unroll
            for (int q = 0; q < 4; q++) acc[mf][nf][q] = 0.f;

    for (int k0 = 0; k0 < D; k0 += KC) {
        __syncthreads();
        #pragma unroll
        for (int it = 0; it < 2; it++) {
            int u = tid + it * 256;
            int r = u >> 2;
            int seg = u & 3;
            const size_t goff = (size_t)r * D + k0 + seg * 8;
            const int soff = r * SROW + seg * 8;
            *(float4*)(sAhi + soff) = __ldg((const float4*)(Ahi + (size_t)rowA * D + goff));
            *(float4*)(sAlo + soff) = __ldg((const float4*)(Alo + (size_t)rowA * D + goff));
            *(float4*)(sBhi + soff) = __ldg((const float4*)(Bhi + (size_t)rowB * D + goff));
            *(float4*)(sBlo + soff) = __ldg((const float4*)(Blo + (size_t)rowB * D + goff));
        }
        __syncthreads();

        #pragma unroll
        for (int ks = 0; ks < 2; ks++) {
            const int kb = ks * 16;
            uint32_t ah[2][4], al[2][4];
            #pragma unroll
            for (int mf = 0; mf < 2; mf++) {
                const int r0 = wm * 32 + mf * 16 + g;
                const int c0 = kb + tg * 2;
                ah[mf][0] = *(const uint32_t*)(sAhi + r0 * SROW + c0);
                ah[mf][1] = *(const uint32_t*)(sAhi + (r0 + 8) * SROW + c0);
                ah[mf][2] = *(const uint32_t*)(sAhi + r0 * SROW + c0 + 8);
                ah[mf][3] = *(const uint32_t*)(sAhi + (r0 + 8) * SROW + c0 + 8);
                al[mf][0] = *(const uint32_t*)(sAlo + r0 * SROW + c0);
                al[mf][1] = *(const uint32_t*)(sAlo + (r0 + 8) * SROW + c0);
                al[mf][2] = *(const uint32_t*)(sAlo + r0 * SROW + c0 + 8);
                al[mf][3] = *(const uint32_t*)(sAlo + (r0 + 8) * SROW + c0 + 8);
            }
            #pragma unroll
            for (int nf = 0; nf < 8; nf++) {
                const int n0 = wn * 64 + nf * 8 + g;
                const int c0 = kb + tg * 2;
                uint32_t bh[2], bl[2];
                bh[0] = *(const uint32_t*)(sBhi + n0 * SROW + c0);
                bh[1] = *(const uint32_t*)(sBhi + n0 * SROW + c0 + 8);
                bl[0] = *(const uint32_t*)(sBlo + n0 * SROW + c0);
                bl[1] = *(const uint32_t*)(sBlo + n0 * SROW + c0 + 8);
                #pragma unroll
                for (int mf = 0; mf < 2; mf++) {
                    mma_bf16(acc[mf][nf], ah[mf], bh);
                    mma_bf16(acc[mf][nf], ah[mf], bl);
                    mma_bf16(acc[mf][nf], al[mf], bh);
                }
            }
        }
    }
    __syncthreads();

    // ---------------- epilogue: write fp32 Cs + track mins ----------------
    #pragma unroll
    for (int mf = 0; mf < 2; mf++) {
        const int rl0 = wm * 32 + mf * 16 + g;
        const int r0 = by * 128 + rl0;
        const int r1 = r0 + 8;
        const float a20 = __ldg(a2 + r0);
        const float a21 = __ldg(a2 + r1);
        float rm0 = __int_as_float(0x7F7FFFFF), rm1 = rm0;
        #pragma unroll
        for (int nf = 0; nf < 8; nf++) {
            const int cl = wn * 64 + nf * 8 + tg * 2;
            const int c0 = bx * 128 + cl;
            const float b20 = __ldg(b2 + c0);
            const float b21 = __ldg(b2 + c0 + 1);
            float v00 = fminf(fmaxf(a20 + b20 - 2.0f * acc[mf][nf][0], 0.f), 1.0e6f) * KSCALE;
            float v01 = fminf(fmaxf(a20 + b21 - 2.0f * acc[mf][nf][1], 0.f), 1.0e6f) * KSCALE;
            float v10 = fminf(fmaxf(a21 + b20 - 2.0f * acc[mf][nf][2], 0.f), 1.0e6f) * KSCALE;
            float v11 = fminf(fmaxf(a21 + b21 - 2.0f * acc[mf][nf][3], 0.f), 1.0e6f) * KSCALE;

            *(float2*)(Cout + (size_t)r0 * N + c0) = make_float2(v00, v01);
            *(float2*)(Cout + (size_t)r1 * N + c0) = make_float2(v10, v11);
            if (SYM && bx != by) {
                float* t0 = Cout + (size_t)c0 * N;
                float* t1 = Cout + (size_t)(c0 + 1) * N;
                t0[r0] = v00; t0[r1] = v10;
                t1[r0] = v01; t1[r1] = v11;
            }
            rm0 = fminf(rm0, fminf(v00, v01));
            rm1 = fminf(rm1, fminf(v10, v11));
            atomicMin(&sCmin[cl],     __float_as_int(fminf(v00, v10)));
            atomicMin(&sCmin[cl + 1], __float_as_int(fminf(v01, v11)));
        }
        atomicMin(&sRmin[rl0],     __float_as_int(rm0));
        atomicMin(&sRmin[rl0 + 8], __float_as_int(rm1));
    }
    __syncthreads();
    if (tid < 128) {
        atomicMin(&rminArr[rowA + tid], sRmin[tid]);
        atomicMin(&cminArr[rowB + tid], sCmin[tid]);
    }
}

// ---------------- quantize fp32 -> fp16 delta (+ optional transpose) -------
template <bool TRANS>
__global__ void quantize_kernel(const float* __restrict__ in,
                                const int* __restrict__ rminb,
                                const int* __restrict__ cminb,
                                __half* __restrict__ outN,
                                __half* __restrict__ outT)
{
    __shared__ float tile[32][33];
    const int x = blockIdx.x * 32 + threadIdx.x;
    #pragma unroll
    for (int k = 0; k < 4; k++) {
        int yy = blockIdx.y * 32 + threadIdx.y + k * 8;
        float v = __ldg(in + (size_t)yy * N + x);
        tile[threadIdx.y + k * 8][threadIdx.x] = v;
        float ref = __int_as_float(__ldg(rminb + yy));
        outN[(size_t)yy * N + x] = __float2half_rn(v - ref);
    }
    if (TRANS) {
        __syncthreads();
        const int xo = blockIdx.y * 32 + threadIdx.x;
        #pragma unroll
        for (int k = 0; k < 4; k++) {
            int yo = blockIdx.x * 32 + threadIdx.y + k * 8;
            float v = tile[threadIdx.x][threadIdx.y + k * 8];
            float ref = __int_as_float(__ldg(cminb + yo));
            outT[(size_t)yo * N + xo] = __float2half_rn(v - ref);
        }
    }
}

// ---------------- potential init ----------------
__global__ void init_pot_kernel() {
    int i = blockIdx.x * 256 + threadIdx.x;
    if (i < 3 * N) {
        (&d_F[0][0])[i] = 0.f;
        (&d_G[0][0])[i] = 0.f;
    }
}

// ---------------- matrix select ----------------
__device__ __forceinline__ void pick_mh(int p, int phase,
                                        const __half*& M, const int*& refb) {
    if (p == 0)      { M = (phase == 0) ? d_ChXY : d_ChYX; refb = (phase == 0) ? d_rmin[0] : d_rmin[1]; }
    else if (p == 1) { M = d_ChXX; refb = d_rmin[2]; }
    else             { M = d_ChYY; refb = d_rmin[3]; }
}

// ---------------- robust half-iteration (online max), fp16 matrix ----------
__device__ __forceinline__ void lse_up(float& m, float& s, float a) {
    if (a <= m) {
        s += ex2f(a - m);
    } else {
        s = fmaf(s, ex2f(m - a), 1.0f);
        m = a;
    }
}

__global__ __launch_bounds__(256) void lse_robust_kernel(int phase) {
    const int p = blockIdx.y;
    const __half* M; const int* refb;
    pick_mh(p, phase, M, refb);
    const float* vin = (phase == 0) ? d_G[p] : d_F[p];
    float* vout      = (phase == 0) ? d_F[p] : d_G[p];

    const int row = blockIdx.x;
    const float ref = __int_as_float(__ldg(refb + row));
    const int col = threadIdx.x * 16;

    float vvr[16];
    #pragma unroll
    for (int k = 0; k < 4; k++) {
        float4 t = __ldg((const float4*)(vin + col + k * 4));
        vvr[k * 4 + 0] = t.x - ref; vvr[k * 4 + 1] = t.y - ref;
        vvr[k * 4 + 2] = t.z - ref; vvr[k * 4 + 3] = t.w - ref;
    }

    const __half* Mr = M + (size_t)row * N + col;
    uint4 h0 = __ldg((const uint4*)Mr);
    uint4 h1 = __ldg((const uint4*)(Mr + 8));
    uint32_t w[8] = {h0.x, h0.y, h0.z, h0.w, h1.x, h1.y, h1.z, h1.w};

    float m = __int_as_float(0xff800000);
    float s = 0.f;
    #pragma unroll
    for (int q = 0; q < 8; q++) {
        float2 dd = __half22float2(*reinterpret_cast<__half2*>(&w[q]));
        lse_up(m, s, vvr[2 * q]     - dd.x);
        lse_up(m, s, vvr[2 * q + 1] - dd.y);
    }

    __shared__ float sm[256], ss[256];
    sm[threadIdx.x] = m;
    ss[threadIdx.x] = s;
    __syncthreads();
    for (int off = 128; off > 0; off >>= 1) {
        if (threadIdx.x < off) {
            float m1 = sm[threadIdx.x], s1 = ss[threadIdx.x];
            float m2 = sm[threadIdx.x + off], s2 = ss[threadIdx.x + off];
            float mm = fmaxf(m1, m2);
            sm[threadIdx.x] = mm;
            ss[threadIdx.x] = fmaf(s1, ex2f(m1 - mm), s2 * ex2f(m2 - mm));
        }
        __syncthreads();
    }
    if (threadIdx.x == 0) {
        // a-values were (v - ref) - (Cs - ref) = v - Cs: ref cancels, so L is
        // exactly sm + log2(ss). (R6 bug: ref was wrongly added back here.)
        float L = sm[0] + log2f(ss[0]);
        vout[row] = 12.0f - L;
        d_L[phase][p][row] = L;
    }
}

// ---------------- fast half-iteration: 8 rows/block, shifted, fp16 --------
#define RPB 8

__global__ __launch_bounds__(256) void lse_fast_kernel(int phase) {
    const int p = blockIdx.y;
    const __half* M; const int* refb;
    pick_mh(p, phase, M, refb);
    const float* vin = (phase == 0) ? d_G[p] : d_F[p];
    float* vout      = (phase == 0) ? d_F[p] : d_G[p];

    const int row0 = blockIdx.x * RPB;
    const int col = threadIdx.x * 16;

    float vv[16];
    #pragma unroll
    for (int k = 0; k < 4; k++) {
        float4 t = __ldg((const float4*)(vin + col + k * 4));
        vv[k * 4 + 0] = t.x; vv[k * 4 + 1] = t.y;
        vv[k * 4 + 2] = t.z; vv[k * 4 + 3] = t.w;
    }

    float Lp[RPB], s[RPB];
    #pragma unroll
    for (int r = 0; r < RPB; r++) {
        Lp[r] = d_L[phase][p][row0 + r];
        const float cr = Lp[r] + __int_as_float(__ldg(refb + row0 + r));
        const __half* Mr = M + (size_t)(row0 + r) * N + col;
        uint4 h0 = __ldg((const uint4*)Mr);
        uint4 h1 = __ldg((const uint4*)(Mr + 8));
        uint32_t w[8] = {h0.x, h0.y, h0.z, h0.w, h1.x, h1.y, h1.z, h1.w};
        float a0 = 0.f, a1 = 0.f;
        #pragma unroll
        for (int q = 0; q < 8; q++) {
            float2 dd = __half22float2(*reinterpret_cast<__half2*>(&w[q]));
            a0 += ex2f((vv[2 * q]     - cr) - dd.x);
            a1 += ex2f((vv[2 * q + 1] - cr) - dd.y);
        }
        s[r] = a0 + a1;
    }

    #pragma unroll
    for (int off = 16; off > 0; off >>= 1) {
        #pragma unroll
        for (int r = 0; r < RPB; r++)
            s[r] += __shfl_down_sync(0xffffffffu, s[r], off);
    }
    __shared__ float sw[RPB][8];
    const int lane = threadIdx.x & 31;
    const int wid  = threadIdx.x >> 5;
    if (lane == 0) {
        #pragma unroll
        for (int r = 0; r < RPB; r++) sw[r][wid] = s[r];
    }
    __syncthreads();
    if (threadIdx.x < RPB) {
        const int r = threadIdx.x;
        float S = 0.f;
        #pragma unroll
        for (int w2 = 0; w2 < 8; w2++) S += sw[r][w2];
        float Lnew = Lp[r] + log2f(S);
        vout[row0 + r] = 12.0f - Lnew;
        d_L[phase][p][row0 + r] = Lnew;
    }
}

// ---------------- final scalar reduce ----------------
__global__ __launch_bounds__(256) void final_reduce_kernel(float* __restrict__ out) {
    __shared__ double sh[3][256];
    const int tid = threadIdx.x;
    double acc0 = 0.0, acc1 = 0.0, acc2 = 0.0;
    for (int j = tid; j < N; j += 256) {
        acc0 += (double)d_F[0][j] + (double)d_G[0][j];
        acc1 += (double)d_F[1][j] + (double)d_G[1][j];
        acc2 += (double)d_F[2][j] + (double)d_G[2][j];
    }
    sh[0][tid] = acc0; sh[1][tid] = acc1; sh[2][tid] = acc2;
    __syncthreads();
    for (int off = 128; off > 0; off >>= 1) {
        if (tid < off) {
            sh[0][tid] += sh[0][tid + off];
            sh[1][tid] += sh[1][tid + off];
            sh[2][tid] += sh[2][tid + off];
        }
        __syncthreads();
    }
    if (tid == 0) {
        double Sdiff = sh[0][0] - 0.5 * (sh[1][0] + sh[2][0]);
        double val = Sdiff * OUT_SCALE;
        out[0] = (float)(val > 0.0 ? val : 0.0);
    }
}

// ---------------- launch ----------------
extern "C" void kernel_launch(void* const* d_in, const int* in_sizes, int n_in,
                              void* d_out, int out_size)
{
    const float* x = (const float*)d_in[0];
    const float* y = (const float*)d_in[1];
    float* out = (float*)d_out;

    float *Ctmp, *xsq, *ysq;
    __half *ChXY, *ChYX, *ChXX, *ChYY;
    int *rminA;
    __nv_bfloat16 *xhi, *xlo, *yhi, *ylo;
    cudaGetSymbolAddress((void**)&Ctmp, d_Ctmp);
    cudaGetSymbolAddress((void**)&ChXY, d_ChXY);
    cudaGetSymbolAddress((void**)&ChYX, d_ChYX);
    cudaGetSymbolAddress((void**)&ChXX, d_ChXX);
    cudaGetSymbolAddress((void**)&ChYY, d_ChYY);
    cudaGetSymbolAddress((void**)&rminA, d_rmin);
    cudaGetSymbolAddress((void**)&xsq, d_xsq);
    cudaGetSymbolAddress((void**)&ysq, d_ysq);
    cudaGetSymbolAddress((void**)&xhi, d_xhi);
    cudaGetSymbolAddress((void**)&xlo, d_xlo);
    cudaGetSymbolAddress((void**)&yhi, d_yhi);
    cudaGetSymbolAddress((void**)&ylo, d_ylo);

    int* rmXY = rminA + 0 * N;
    int* rmYX = rminA + 1 * N;
    int* rmXX = rminA + 2 * N;
    int* rmYY = rminA + 3 * N;

    convert_kernel<<<(N * D) / 256, 256>>>(x, xhi, xlo);
    convert_kernel<<<(N * D) / 256, 256>>>(y, yhi, ylo);

    dim3 rsBlock(32, 8);
    rowsq_kernel<<<N / 8, rsBlock>>>(x, xsq);
    rowsq_kernel<<<N / 8, rsBlock>>>(y, ysq);

    init_min_kernel<<<(4 * N + 255) / 256, 256>>>();

    dim3 qGrid(N / 32, N / 32);
    dim3 qBlock(32, 8);

    tc_gemm_kernel<false><<<NT * NT, 256>>>(xhi, xlo, yhi, ylo, xsq, ysq, Ctmp, rmXY, rmYX);
    quantize_kernel<true><<<qGrid, qBlock>>>(Ctmp, rmXY, rmYX, ChXY, ChYX);

    tc_gemm_kernel<true><<<NTRI, 256>>>(xhi, xlo, xhi, xlo, xsq, xsq, Ctmp, rmXX, rmXX);
    quantize_kernel<false><<<qGrid, qBlock>>>(Ctmp, rmXX, nullptr, ChXX, nullptr);

    tc_gemm_kernel<true><<<NTRI, 256>>>(yhi, ylo, yhi, ylo, ysq, ysq, Ctmp, rmYY, rmYY);
    quantize_kernel<false><<<qGrid, qBlock>>>(Ctmp, rmYY, nullptr, ChYY, nullptr);

    init_pot_kernel<<<(3 * N + 255) / 256, 256>>>();

    dim3 rGrid(N, 3);
    dim3 fGrid(N / RPB, 3);
    const int WARMUP = 3;
    for (int it = 0; it < WARMUP; it++) {
        lse_robust_kernel<<<rGrid, 256>>>(0);
        lse_robust_kernel<<<rGrid, 256>>>(1);
    }
    for (int it = WARMUP; it < 50; it++) {
        lse_fast_kernel<<<fGrid, 256>>>(0);
        lse_fast_kernel<<<fGrid, 256>>>(1);
    }

    final_reduce_kernel<<<1, 256>>>(out);
}